// round 9
// baseline (speedup 1.0000x reference)
#include <cuda_runtime.h>
#include <cuda_fp16.h>
#include <cstdint>
#include <math.h>

#define D 32
#define H 128
#define THREADS 128
#define TILE_M 64
#define NROWS 65536

__device__ __forceinline__ uint32_t pack_h2(__half a, __half b) {
    return (uint32_t)__half_as_ushort(a) | ((uint32_t)__half_as_ushort(b) << 16);
}
__device__ __forceinline__ uint32_t cvt_h2(float a, float b) {
    uint32_t r;
    asm("cvt.rn.f16x2.f32 %0, %2, %1;" : "=r"(r) : "f"(a), "f"(b));
    return r;
}
// fp16 2-way split: v = h1 + h2 with |h2| ~ 2^-11 |v|
__device__ __forceinline__ void split2h(float vx, float vy, uint32_t& p1, uint32_t& p2) {
    __half hx = __float2half_rn(vx);
    __half hy = __float2half_rn(vy);
    float rx = vx - __half2float(hx);
    float ry = vy - __half2float(hy);
    p1 = pack_h2(hx, hy);
    p2 = cvt_h2(rx, ry);
}
__device__ __forceinline__ float tanh_ap(float x) {
    float y;
    asm("tanh.approx.f32 %0, %1;" : "=f"(y) : "f"(x));
    return y;
}
__device__ __forceinline__ void mma_f16(float* d, const uint32_t* a, uint32_t b0, uint32_t b1) {
    asm volatile(
        "mma.sync.aligned.m16n8k16.row.col.f32.f16.f16.f32 "
        "{%0,%1,%2,%3}, {%4,%5,%6,%7}, {%8,%9}, {%0,%1,%2,%3};"
        : "+f"(d[0]), "+f"(d[1]), "+f"(d[2]), "+f"(d[3])
        : "r"(a[0]), "r"(a[1]), "r"(a[2]), "r"(a[3]), "r"(b0), "r"(b1));
}

// ---------------- single fused kernel ----------------
extern "C" __global__ void __launch_bounds__(THREADS, 4)
stein_main(const float* __restrict__ x,
           const float* __restrict__ W1,
           const float* __restrict__ b1,
           const float* __restrict__ W2,
           const float* __restrict__ b2,
           const float* __restrict__ theta,
           float* __restrict__ out)
{
    // z-side fp16 B-frag table (built once per CTA):
    // entry e = ((nt*2 + ks)*32 + lane)*2 + j,  nt 0..15 : B[n][k] = W1[k][n]
    __shared__ uint32_t s_Bfz[2048];     // 8 KB
    __shared__ float s_cs[H];
    __shared__ float s_base[TILE_M];
    __shared__ float s_part[TILE_M][2];

    const int tid  = threadIdx.x;
    const int lane = tid & 31;
    const int w    = tid >> 5;
    const int mh   = w >> 1;        // row half (0: rows 0-31, 1: rows 32-63)
    const int kh   = w & 1;         // hidden-unit half (cols 0-63 / 64-127)
    const int row0 = blockIdx.x * TILE_M;

    // ---- one-time z-frag build: strided map so adjacent lanes read adjacent n ----
    #pragma unroll
    for (int q = 0; q < 16; q++) {
        const int e  = tid + 128 * q;
        const int j  = e & 1;
        const int l  = (e >> 1) & 31;
        const int ks = (e >> 6) & 1;
        const int nt = e >> 7;
        const int n  = nt * 8 + (l >> 2);
        const int k0 = ks * 16 + 2 * (l & 3) + j * 8;
        s_Bfz[e] = cvt_h2(__ldg(W1 + k0 * H + n), __ldg(W1 + (k0 + 1) * H + n));
    }

    // ---- c_k = sum_i W1[i,k] W2[k,i] (coalesced: consecutive tid -> consecutive k) ----
    {
        const int k = tid;
        const float4* w2r = (const float4*)(W2 + k * D);
        float c = 0.0f;
        #pragma unroll
        for (int i = 0; i < D; i += 4) {
            float4 wv = __ldg(w2r + (i >> 2));
            c = fmaf(__ldg(W1 + (i + 0) * H + k), wv.x, c);
            c = fmaf(__ldg(W1 + (i + 1) * H + k), wv.y, c);
            c = fmaf(__ldg(W1 + (i + 2) * H + k), wv.z, c);
            c = fmaf(__ldg(W1 + (i + 3) * H + k), wv.w, c);
        }
        s_cs[k] = c;
    }

    // ---- prologue: s_base[r] = theta - x[r].b2 (exact fp32) ----
    if (tid < TILE_M) {
        const float4* xr  = (const float4*)(x + (size_t)(row0 + tid) * D);
        const float4* b2v = (const float4*)b2;
        float s = __ldg(theta);
        #pragma unroll
        for (int i = 0; i < D / 4; i++) {
            float4 a = __ldg(xr + i);
            float4 b = __ldg(b2v + i);
            s = fmaf(-a.x, b.x, s);
            s = fmaf(-a.y, b.y, s);
            s = fmaf(-a.z, b.z, s);
            s = fmaf(-a.w, b.w, s);
        }
        s_base[tid] = s;
    }

    // ---- A fragments straight from gmem (frag order, fp16 h1/h2 split) ----
    const int Mbase = row0 + mh * 32;
    uint32_t a1[2][2][4], a2[2][2][4];           // [mt][ks][frag]
    #pragma unroll
    for (int mt = 0; mt < 2; mt++) {
        const int r = Mbase + mt * 16 + (lane >> 2);
        #pragma unroll
        for (int ks = 0; ks < 2; ks++) {
            const int c = ks * 16 + 2 * (lane & 3);
            float2 v00 = __ldg((const float2*)(x + (size_t)r       * D + c));
            float2 v10 = __ldg((const float2*)(x + (size_t)(r + 8) * D + c));
            float2 v01 = __ldg((const float2*)(x + (size_t)r       * D + c + 8));
            float2 v11 = __ldg((const float2*)(x + (size_t)(r + 8) * D + c + 8));
            split2h(v00.x, v00.y, a1[mt][ks][0], a2[mt][ks][0]);
            split2h(v10.x, v10.y, a1[mt][ks][1], a2[mt][ks][1]);
            split2h(v01.x, v01.y, a1[mt][ks][2], a2[mt][ks][2]);
            split2h(v11.x, v11.y, a1[mt][ks][3], a2[mt][ks][3]);
        }
    }
    __syncthreads();   // s_Bfz / s_cs / s_base ready

    // v-side per-lane global pointer: B[np][k] = W2[np][k], contiguous in k
    const int k0l = 2 * (lane & 3);
    const float* pv = W2 + (size_t)(kh * 64 + (lane >> 2)) * D + k0l;

    // ---- mainloop: per-p MMA slab (2-pass fp16), folded into psum ----
    float psum[4] = {0.f, 0.f, 0.f, 0.f};

    #pragma unroll 4
    for (int p = 0; p < 8; p++) {
        const int ntz = kh * 8 + p;
        uint2 bz[2], bv[2];                       // [ks]
        #pragma unroll
        for (int ks = 0; ks < 2; ks++) {
            bz[ks] = *(const uint2*)&s_Bfz[((ntz * 2 + ks) * 32 + lane) * 2];  // LDS.64
            const float* pvk = pv + (size_t)p * 8 * D + ks * 16;
            float2 v0 = __ldg((const float2*)(pvk));
            float2 v1 = __ldg((const float2*)(pvk + 8));
            bv[ks].x = cvt_h2(v0.x, v0.y);
            bv[ks].y = cvt_h2(v1.x, v1.y);
        }

        float accz[2][4], accv[2][4];             // [mt][frag]
        #pragma unroll
        for (int mt = 0; mt < 2; mt++)
            #pragma unroll
            for (int e = 0; e < 4; e++) { accz[mt][e] = 0.f; accv[mt][e] = 0.f; }

        #pragma unroll
        for (int mt = 0; mt < 2; mt++)
            #pragma unroll
            for (int ks = 0; ks < 2; ks++) {
                mma_f16(accz[mt], a1[mt][ks], bz[ks].x, bz[ks].y);  // h1 pass
                mma_f16(accv[mt], a1[mt][ks], bv[ks].x, bv[ks].y);
                mma_f16(accz[mt], a2[mt][ks], bz[ks].x, bz[ks].y);  // h2 pass
                mma_f16(accv[mt], a2[mt][ks], bv[ks].x, bv[ks].y);
            }

        // --- epilogue fold for this p-slab ---
        const int kbase = kh * 64 + p * 8 + k0l;
        const float2 b1p = __ldg((const float2*)(b1 + kbase));
        const float2 csp = *(const float2*)(s_cs + kbase);
        #pragma unroll
        for (int j = 0; j < 2; j++) {
            const float b1k = j ? b1p.y : b1p.x;
            const float ck  = j ? csp.y : csp.x;
            #pragma unroll
            for (int mt = 0; mt < 2; mt++)
                #pragma unroll
                for (int rs = 0; rs < 2; rs++) {
                    float z = accz[mt][rs * 2 + j] + b1k;
                    float v = accv[mt][rs * 2 + j];
                    float h = tanh_ap(z);
                    float g = fmaf(-h, h, 1.0f);
                    float& ps = psum[mt * 2 + rs];
                    ps = fmaf(g, ck, ps);
                    ps = fmaf(-h, v, ps);
                }
        }
    }

    // quad reduction over the 4 lanes sharing the same rows
    #pragma unroll
    for (int i = 0; i < 4; i++) {
        psum[i] += __shfl_xor_sync(0xFFFFFFFFu, psum[i], 1);
        psum[i] += __shfl_xor_sync(0xFFFFFFFFu, psum[i], 2);
    }
    if ((lane & 3) == 0) {
        const int rbase = mh * 32 + (lane >> 2);
        s_part[rbase +  0][kh] = psum[0];
        s_part[rbase +  8][kh] = psum[1];
        s_part[rbase + 16][kh] = psum[2];
        s_part[rbase + 24][kh] = psum[3];
    }
    __syncthreads();

    if (tid < TILE_M)
        out[row0 + tid] = s_base[tid] + s_part[tid][0] + s_part[tid][1];
}

extern "C" void kernel_launch(void* const* d_in, const int* in_sizes, int n_in,
                              void* d_out, int out_size)
{
    const float* x     = (const float*)d_in[0];
    const float* W1    = (const float*)d_in[1];
    const float* b1    = (const float*)d_in[2];
    const float* W2    = (const float*)d_in[3];
    const float* b2    = (const float*)d_in[4];
    const float* theta = (const float*)d_in[5];
    float*       out   = (float*)d_out;

    const int nrows = in_sizes[0] / D;          // 65536
    const int grid  = nrows / TILE_M;           // 1024

    stein_main<<<grid, THREADS>>>(x, W1, b1, W2, b2, theta, out);
}

// round 10
// speedup vs baseline: 1.2775x; 1.2775x over previous
#include <cuda_runtime.h>
#include <cuda_fp16.h>
#include <cstdint>
#include <math.h>

#define D 32
#define H 128
#define THREADS 128
#define TILE_M 64
#define NROWS 65536

__device__ __forceinline__ uint32_t cvt_h2(float a, float b) {
    uint32_t r;
    asm("cvt.rn.f16x2.f32 %0, %2, %1;" : "=r"(r) : "f"(a), "f"(b));
    return r;
}
__device__ __forceinline__ uint32_t pack_h2(__half a, __half b) {
    return (uint32_t)__half_as_ushort(a) | ((uint32_t)__half_as_ushort(b) << 16);
}
// fp16 2-way split: v = h1 + h2 with |h2| ~ 2^-11 |v|
__device__ __forceinline__ void split2h(float vx, float vy, uint32_t& p1, uint32_t& p2) {
    __half hx = __float2half_rn(vx);
    __half hy = __float2half_rn(vy);
    float rx = vx - __half2float(hx);
    float ry = vy - __half2float(hy);
    p1 = pack_h2(hx, hy);
    p2 = cvt_h2(rx, ry);
}
__device__ __forceinline__ float tanh_ap(float x) {
    float y;
    asm("tanh.approx.f32 %0, %1;" : "=f"(y) : "f"(x));
    return y;
}
__device__ __forceinline__ void mma_f16(float* d, const uint32_t* a, uint32_t b0, uint32_t b1) {
    asm volatile(
        "mma.sync.aligned.m16n8k16.row.col.f32.f16.f16.f32 "
        "{%0,%1,%2,%3}, {%4,%5,%6,%7}, {%8,%9}, {%0,%1,%2,%3};"
        : "+f"(d[0]), "+f"(d[1]), "+f"(d[2]), "+f"(d[3])
        : "r"(a[0]), "r"(a[1]), "r"(a[2]), "r"(a[3]), "r"(b0), "r"(b1));
}

// ---------------- single fused kernel ----------------
extern "C" __global__ void __launch_bounds__(THREADS, 4)
stein_main(const float* __restrict__ x,
           const float* __restrict__ W1,
           const float* __restrict__ b1,
           const float* __restrict__ W2,
           const float* __restrict__ b2,
           const float* __restrict__ theta,
           float* __restrict__ out)
{
    // fp16 B-frag tables in HMMA order, built once per CTA with COALESCED reads.
    // Entry ((nt*2 + ks)*32 + lane)*2 + j holds pair {B[n][k], B[n][k+1]},
    //   n = nt*8 + (lane>>2),  k = ks*16 + 2*(lane&3) + j*8.
    __shared__ uint32_t s_Bfz[2048];   // z GEMM: B[n][k] = W1[k][n]   (8 KB)
    __shared__ uint32_t s_Bfv[2048];   // v GEMM: B[n][k] = W2[n][k]   (8 KB)
    __shared__ float s_cs[H];
    __shared__ float s_base[TILE_M];
    __shared__ float s_part[TILE_M][2];

    const int tid  = threadIdx.x;
    const int lane = tid & 31;
    const int w    = tid >> 5;
    const int mh   = w >> 1;        // row half (0: rows 0-31, 1: rows 32-63)
    const int kh   = w & 1;         // hidden-unit half (cols 0-63 / 64-127)
    const int row0 = blockIdx.x * TILE_M;

    // ---- z-frag build: 16 coalesced W1 row-pair reads (thread tid <-> col n) ----
    // k0 = ks*16 + 2*t + jj*8 ; entry l = (n&7)*4 + t
    #pragma unroll
    for (int it = 0; it < 16; it++) {
        const int ks = it >> 3, jj = (it >> 2) & 1, t = it & 3;
        const int k0 = ks * 16 + 2 * t + jj * 8;
        const float w0 = __ldg(W1 + k0 * H + tid);         // coalesced row k0
        const float w1 = __ldg(W1 + (k0 + 1) * H + tid);   // coalesced row k0+1
        const int nt = tid >> 3;
        const int l  = (tid & 7) * 4 + t;
        s_Bfz[((nt * 2 + ks) * 32 + l) * 2 + jj] = cvt_h2(w0, w1);
    }
    // ---- v-frag build: 16 linear float2 reads of W2 (row-major [128][32]) ----
    #pragma unroll
    for (int it = 0; it < 16; it++) {
        const int f = it * THREADS + tid;                  // float2 index, linear
        const float2 v = __ldg((const float2*)W2 + f);
        const int np = f >> 4;                             // W2 row (hidden unit)
        const int k0 = (f & 15) * 2;                       // even col
        const int nt = np >> 3;
        const int ks = k0 >> 4, r = k0 & 15;
        const int jj = r >> 3, t = (r & 7) >> 1;
        const int l  = (np & 7) * 4 + t;
        s_Bfv[((nt * 2 + ks) * 32 + l) * 2 + jj] = cvt_h2(v.x, v.y);
    }

    // ---- c_k = sum_i W1[i,k] W2[k,i] (coalesced; one-time) ----
    {
        const int k = tid;
        const float4* w2r = (const float4*)(W2 + k * D);
        float c = 0.0f;
        #pragma unroll
        for (int i = 0; i < D; i += 4) {
            float4 wv = __ldg(w2r + (i >> 2));
            c = fmaf(__ldg(W1 + (i + 0) * H + k), wv.x, c);
            c = fmaf(__ldg(W1 + (i + 1) * H + k), wv.y, c);
            c = fmaf(__ldg(W1 + (i + 2) * H + k), wv.z, c);
            c = fmaf(__ldg(W1 + (i + 3) * H + k), wv.w, c);
        }
        s_cs[k] = c;
    }

    // ---- prologue: s_base[r] = theta - x[r].b2 (exact fp32) ----
    if (tid < TILE_M) {
        const float4* xr  = (const float4*)(x + (size_t)(row0 + tid) * D);
        const float4* b2v = (const float4*)b2;
        float s = __ldg(theta);
        #pragma unroll
        for (int i = 0; i < D / 4; i++) {
            float4 a = __ldg(xr + i);
            float4 b = __ldg(b2v + i);
            s = fmaf(-a.x, b.x, s);
            s = fmaf(-a.y, b.y, s);
            s = fmaf(-a.z, b.z, s);
            s = fmaf(-a.w, b.w, s);
        }
        s_base[tid] = s;
    }

    // ---- A fragments straight from gmem (frag order, fp16 h1/h2 split) ----
    const int Mbase = row0 + mh * 32;
    uint32_t a1[2][2][4], a2[2][2][4];           // [mt][ks][frag]
    #pragma unroll
    for (int mt = 0; mt < 2; mt++) {
        const int r = Mbase + mt * 16 + (lane >> 2);
        #pragma unroll
        for (int ks = 0; ks < 2; ks++) {
            const int c = ks * 16 + 2 * (lane & 3);
            float2 v00 = __ldg((const float2*)(x + (size_t)r       * D + c));
            float2 v10 = __ldg((const float2*)(x + (size_t)(r + 8) * D + c));
            float2 v01 = __ldg((const float2*)(x + (size_t)r       * D + c + 8));
            float2 v11 = __ldg((const float2*)(x + (size_t)(r + 8) * D + c + 8));
            split2h(v00.x, v00.y, a1[mt][ks][0], a2[mt][ks][0]);
            split2h(v10.x, v10.y, a1[mt][ks][1], a2[mt][ks][1]);
            split2h(v01.x, v01.y, a1[mt][ks][2], a2[mt][ks][2]);
            split2h(v11.x, v11.y, a1[mt][ks][3], a2[mt][ks][3]);
        }
    }
    __syncthreads();   // frag tables / s_cs / s_base ready

    // ---- mainloop: per-p MMA slab (2-pass fp16), folded into psum ----
    const int k0l = 2 * (lane & 3);
    float psum[4] = {0.f, 0.f, 0.f, 0.f};

    #pragma unroll 4
    for (int p = 0; p < 8; p++) {
        const int nt = kh * 8 + p;
        uint2 bz[2], bv[2];                       // [ks] — LDS.64, 2-phase
        #pragma unroll
        for (int ks = 0; ks < 2; ks++) {
            bz[ks] = *(const uint2*)&s_Bfz[((nt * 2 + ks) * 32 + lane) * 2];
            bv[ks] = *(const uint2*)&s_Bfv[((nt * 2 + ks) * 32 + lane) * 2];
        }

        float accz[2][4], accv[2][4];             // [mt][frag]
        #pragma unroll
        for (int mt = 0; mt < 2; mt++)
            #pragma unroll
            for (int e = 0; e < 4; e++) { accz[mt][e] = 0.f; accv[mt][e] = 0.f; }

        #pragma unroll
        for (int mt = 0; mt < 2; mt++)
            #pragma unroll
            for (int ks = 0; ks < 2; ks++) {
                mma_f16(accz[mt], a1[mt][ks], bz[ks].x, bz[ks].y);  // h1 pass
                mma_f16(accv[mt], a1[mt][ks], bv[ks].x, bv[ks].y);
                mma_f16(accz[mt], a2[mt][ks], bz[ks].x, bz[ks].y);  // h2 pass
                mma_f16(accv[mt], a2[mt][ks], bv[ks].x, bv[ks].y);
            }

        // --- epilogue fold for this p-slab ---
        const int kbase = kh * 64 + p * 8 + k0l;
        const float2 b1p = __ldg((const float2*)(b1 + kbase));
        const float2 csp = *(const float2*)(s_cs + kbase);
        #pragma unroll
        for (int j = 0; j < 2; j++) {
            const float b1k = j ? b1p.y : b1p.x;
            const float ck  = j ? csp.y : csp.x;
            #pragma unroll
            for (int mt = 0; mt < 2; mt++)
                #pragma unroll
                for (int rs = 0; rs < 2; rs++) {
                    float z = accz[mt][rs * 2 + j] + b1k;
                    float v = accv[mt][rs * 2 + j];
                    float h = tanh_ap(z);
                    float g = fmaf(-h, h, 1.0f);
                    float& ps = psum[mt * 2 + rs];
                    ps = fmaf(g, ck, ps);
                    ps = fmaf(-h, v, ps);
                }
        }
    }

    // quad reduction over the 4 lanes sharing the same rows
    #pragma unroll
    for (int i = 0; i < 4; i++) {
        psum[i] += __shfl_xor_sync(0xFFFFFFFFu, psum[i], 1);
        psum[i] += __shfl_xor_sync(0xFFFFFFFFu, psum[i], 2);
    }
    if ((lane & 3) == 0) {
        const int rbase = mh * 32 + (lane >> 2);
        s_part[rbase +  0][kh] = psum[0];
        s_part[rbase +  8][kh] = psum[1];
        s_part[rbase + 16][kh] = psum[2];
        s_part[rbase + 24][kh] = psum[3];
    }
    __syncthreads();

    if (tid < TILE_M)
        out[row0 + tid] = s_base[tid] + s_part[tid][0] + s_part[tid][1];
}

extern "C" void kernel_launch(void* const* d_in, const int* in_sizes, int n_in,
                              void* d_out, int out_size)
{
    const float* x     = (const float*)d_in[0];
    const float* W1    = (const float*)d_in[1];
    const float* b1    = (const float*)d_in[2];
    const float* W2    = (const float*)d_in[3];
    const float* b2    = (const float*)d_in[4];
    const float* theta = (const float*)d_in[5];
    float*       out   = (float*)d_out;

    const int nrows = in_sizes[0] / D;          // 65536
    const int grid  = nrows / TILE_M;           // 1024

    stein_main<<<grid, THREADS>>>(x, W1, b1, W2, b2, theta, out);
}

// round 11
// speedup vs baseline: 1.3879x; 1.0864x over previous
#include <cuda_runtime.h>
#include <cuda_fp16.h>
#include <cstdint>
#include <math.h>

#define D 32
#define H 128
#define THREADS 256
#define ROWS_CTA 256
#define PASS_ROWS 128
#define NROWS 65536

__device__ __forceinline__ uint32_t cvt_h2(float a, float b) {
    uint32_t r;
    asm("cvt.rn.f16x2.f32 %0, %2, %1;" : "=r"(r) : "f"(a), "f"(b));
    return r;
}
__device__ __forceinline__ uint32_t pack_h2(__half a, __half b) {
    return (uint32_t)__half_as_ushort(a) | ((uint32_t)__half_as_ushort(b) << 16);
}
// fp16 2-way split: v = h1 + h2 with |h2| ~ 2^-11 |v|
__device__ __forceinline__ void split2h(float vx, float vy, uint32_t& p1, uint32_t& p2) {
    __half hx = __float2half_rn(vx);
    __half hy = __float2half_rn(vy);
    float rx = vx - __half2float(hx);
    float ry = vy - __half2float(hy);
    p1 = pack_h2(hx, hy);
    p2 = cvt_h2(rx, ry);
}
__device__ __forceinline__ float tanh_ap(float x) {
    float y;
    asm("tanh.approx.f32 %0, %1;" : "=f"(y) : "f"(x));
    return y;
}
__device__ __forceinline__ void mma_f16(float* d, const uint32_t* a, uint32_t b0, uint32_t b1) {
    asm volatile(
        "mma.sync.aligned.m16n8k16.row.col.f32.f16.f16.f32 "
        "{%0,%1,%2,%3}, {%4,%5,%6,%7}, {%8,%9}, {%0,%1,%2,%3};"
        : "+f"(d[0]), "+f"(d[1]), "+f"(d[2]), "+f"(d[3])
        : "r"(a[0]), "r"(a[1]), "r"(a[2]), "r"(a[3]), "r"(b0), "r"(b1));
}

// ---------------- single fused kernel ----------------
extern "C" __global__ void __launch_bounds__(THREADS, 2)
stein_main(const float* __restrict__ x,
           const float* __restrict__ W1,
           const float* __restrict__ b1,
           const float* __restrict__ W2,
           const float* __restrict__ b2,
           const float* __restrict__ theta,
           float* __restrict__ out)
{
    // fp16 B-frag tables in HMMA order (same mapping as R10, build split over 256 thr)
    __shared__ uint32_t s_Bfz[2048];   // z GEMM: B[n][k] = W1[k][n]  (8 KB)
    __shared__ uint32_t s_Bfv[2048];   // v GEMM: B[n][k] = W2[n][k]  (8 KB)
    __shared__ float s_cs[H];
    __shared__ float s_b1[H];
    __shared__ float s_part[PASS_ROWS][2];

    const int tid  = threadIdx.x;
    const int lane = tid & 31;
    const int w    = tid >> 5;       // 0..7
    const int mh   = w >> 1;         // 0..3 : 32-row slab within the 128-row pass
    const int kh   = w & 1;          // hidden-unit half (cols 0-63 / 64-127)
    const int row0 = blockIdx.x * ROWS_CTA;

    // ---- z-frag build: coalesced W1 row reads (thread n = tid&127) ----
    {
        const int n = tid & 127;
        const int itbase = (tid >> 7) * 8;
        #pragma unroll
        for (int q = 0; q < 8; q++) {
            const int it = itbase + q;
            const int ks = it >> 3, jj = (it >> 2) & 1, t = it & 3;
            const int k0 = ks * 16 + 2 * t + jj * 8;
            const float w0 = __ldg(W1 + k0 * H + n);
            const float w1 = __ldg(W1 + (k0 + 1) * H + n);
            const int nt = n >> 3;
            const int l  = (n & 7) * 4 + t;
            s_Bfz[((nt * 2 + ks) * 32 + l) * 2 + jj] = cvt_h2(w0, w1);
        }
    }
    // ---- v-frag build: linear float2 reads of W2 ----
    #pragma unroll
    for (int q = 0; q < 8; q++) {
        const int f = q * THREADS + tid;
        const float2 v = __ldg((const float2*)W2 + f);
        const int np = f >> 4;
        const int k0 = (f & 15) * 2;
        const int nt = np >> 3;
        const int ks = k0 >> 4, r = k0 & 15;
        const int jj = r >> 3, t = (r & 7) >> 1;
        const int l  = (np & 7) * 4 + t;
        s_Bfv[((nt * 2 + ks) * 32 + l) * 2 + jj] = cvt_h2(v.x, v.y);
    }
    // ---- c_k (tid<128, coalesced) ; b1 staging (tid>=128) ----
    if (tid < H) {
        const int k = tid;
        const float4* w2r = (const float4*)(W2 + k * D);
        float c = 0.0f;
        #pragma unroll
        for (int i = 0; i < D; i += 4) {
            float4 wv = __ldg(w2r + (i >> 2));
            c = fmaf(__ldg(W1 + (i + 0) * H + k), wv.x, c);
            c = fmaf(__ldg(W1 + (i + 1) * H + k), wv.y, c);
            c = fmaf(__ldg(W1 + (i + 2) * H + k), wv.z, c);
            c = fmaf(__ldg(W1 + (i + 3) * H + k), wv.w, c);
        }
        s_cs[k] = c;
    } else {
        s_b1[tid - H] = __ldg(b1 + tid - H);
    }

    // per-lane b2 pairs for the fold (cols c=ks*16+2t and c+8)
    const int k0l = 2 * (lane & 3);
    float2 b2p[2][2];
    #pragma unroll
    for (int ks = 0; ks < 2; ks++) {
        b2p[ks][0] = __ldg((const float2*)(b2 + ks * 16 + k0l));
        b2p[ks][1] = __ldg((const float2*)(b2 + ks * 16 + k0l + 8));
    }
    const float theta_v = __ldg(theta);

    __syncthreads();   // frag tables / s_cs / s_b1 ready

    // ================= two passes of 128 rows =================
    for (int s = 0; s < 2; s++) {
        const int Mbase = row0 + s * PASS_ROWS + mh * 32;

        float psum[4] = {0.f, 0.f, 0.f, 0.f};

        // ---- A fragments + fold -x.b2 (kh==0 warps only) ----
        uint32_t a1[2][2][4], a2[2][2][4];        // [mt][ks][frag]
        #pragma unroll
        for (int mt = 0; mt < 2; mt++) {
            const int r = Mbase + mt * 16 + (lane >> 2);
            #pragma unroll
            for (int ks = 0; ks < 2; ks++) {
                const int c = ks * 16 + k0l;
                float2 v00 = __ldg((const float2*)(x + (size_t)r       * D + c));
                float2 v10 = __ldg((const float2*)(x + (size_t)(r + 8) * D + c));
                float2 v01 = __ldg((const float2*)(x + (size_t)r       * D + c + 8));
                float2 v11 = __ldg((const float2*)(x + (size_t)(r + 8) * D + c + 8));
                split2h(v00.x, v00.y, a1[mt][ks][0], a2[mt][ks][0]);
                split2h(v10.x, v10.y, a1[mt][ks][1], a2[mt][ks][1]);
                split2h(v01.x, v01.y, a1[mt][ks][2], a2[mt][ks][2]);
                split2h(v11.x, v11.y, a1[mt][ks][3], a2[mt][ks][3]);
                if (kh == 0) {
                    float& p0 = psum[mt * 2 + 0];
                    float& p1r = psum[mt * 2 + 1];
                    p0  = fmaf(-v00.x, b2p[ks][0].x, p0);
                    p0  = fmaf(-v00.y, b2p[ks][0].y, p0);
                    p0  = fmaf(-v01.x, b2p[ks][1].x, p0);
                    p0  = fmaf(-v01.y, b2p[ks][1].y, p0);
                    p1r = fmaf(-v10.x, b2p[ks][0].x, p1r);
                    p1r = fmaf(-v10.y, b2p[ks][0].y, p1r);
                    p1r = fmaf(-v11.x, b2p[ks][1].x, p1r);
                    p1r = fmaf(-v11.y, b2p[ks][1].y, p1r);
                }
            }
        }

        // ---- mainloop: per-p MMA slab (2-pass fp16), folded into psum ----
        #pragma unroll 4
        for (int p = 0; p < 8; p++) {
            const int nt = kh * 8 + p;
            uint2 bz[2], bv[2];                   // [ks] — LDS.64, conflict-free
            #pragma unroll
            for (int ks = 0; ks < 2; ks++) {
                bz[ks] = *(const uint2*)&s_Bfz[((nt * 2 + ks) * 32 + lane) * 2];
                bv[ks] = *(const uint2*)&s_Bfv[((nt * 2 + ks) * 32 + lane) * 2];
            }

            float accz[2][4], accv[2][4];         // [mt][frag]
            #pragma unroll
            for (int mt = 0; mt < 2; mt++)
                #pragma unroll
                for (int e = 0; e < 4; e++) { accz[mt][e] = 0.f; accv[mt][e] = 0.f; }

            #pragma unroll
            for (int mt = 0; mt < 2; mt++)
                #pragma unroll
                for (int ks = 0; ks < 2; ks++) {
                    mma_f16(accz[mt], a1[mt][ks], bz[ks].x, bz[ks].y);  // h1
                    mma_f16(accv[mt], a1[mt][ks], bv[ks].x, bv[ks].y);
                    mma_f16(accz[mt], a2[mt][ks], bz[ks].x, bz[ks].y);  // h2
                    mma_f16(accv[mt], a2[mt][ks], bv[ks].x, bv[ks].y);
                }

            // --- epilogue fold for this p-slab (b1/cs from smem) ---
            const int kbase = kh * 64 + p * 8 + k0l;
            const float2 b1p = *(const float2*)(s_b1 + kbase);
            const float2 csp = *(const float2*)(s_cs + kbase);
            #pragma unroll
            for (int j = 0; j < 2; j++) {
                const float b1k = j ? b1p.y : b1p.x;
                const float ck  = j ? csp.y : csp.x;
                #pragma unroll
                for (int mt = 0; mt < 2; mt++)
                    #pragma unroll
                    for (int rs = 0; rs < 2; rs++) {
                        float z = accz[mt][rs * 2 + j] + b1k;
                        float v = accv[mt][rs * 2 + j];
                        float h = tanh_ap(z);
                        float g = fmaf(-h, h, 1.0f);
                        float& ps = psum[mt * 2 + rs];
                        ps = fmaf(g, ck, ps);
                        ps = fmaf(-h, v, ps);
                    }
            }
        }

        // ---- quad reduction + combine halves + write ----
        #pragma unroll
        for (int i = 0; i < 4; i++) {
            psum[i] += __shfl_xor_sync(0xFFFFFFFFu, psum[i], 1);
            psum[i] += __shfl_xor_sync(0xFFFFFFFFu, psum[i], 2);
        }
        if ((lane & 3) == 0) {
            const int rbase = mh * 32 + (lane >> 2);
            s_part[rbase +  0][kh] = psum[0];
            s_part[rbase +  8][kh] = psum[1];
            s_part[rbase + 16][kh] = psum[2];
            s_part[rbase + 24][kh] = psum[3];
        }
        __syncthreads();
        if (tid < PASS_ROWS)
            out[row0 + s * PASS_ROWS + tid] = s_part[tid][0] + s_part[tid][1] + theta_v;
        if (s == 0) __syncthreads();   // protect s_part reuse
    }
}

extern "C" void kernel_launch(void* const* d_in, const int* in_sizes, int n_in,
                              void* d_out, int out_size)
{
    const float* x     = (const float*)d_in[0];
    const float* W1    = (const float*)d_in[1];
    const float* b1    = (const float*)d_in[2];
    const float* W2    = (const float*)d_in[3];
    const float* b2    = (const float*)d_in[4];
    const float* theta = (const float*)d_in[5];
    float*       out   = (float*)d_out;

    const int nrows = in_sizes[0] / D;          // 65536
    const int grid  = nrows / ROWS_CTA;         // 256

    stein_main<<<grid, THREADS>>>(x, W1, b1, W2, b2, theta, out);
}

// round 12
// speedup vs baseline: 1.6307x; 1.1749x over previous
#include <cuda_runtime.h>
#include <cuda_fp16.h>
#include <cstdint>
#include <math.h>

#define D 32
#define H 128
#define THREADS 256
#define ROWS_CTA 256
#define PASS_ROWS 128
#define NROWS 65536

__device__ __forceinline__ uint32_t cvt_h2(float a, float b) {
    uint32_t r;
    asm("cvt.rn.f16x2.f32 %0, %2, %1;" : "=r"(r) : "f"(a), "f"(b));
    return r;
}
__device__ __forceinline__ uint32_t pack_h2(__half a, __half b) {
    return (uint32_t)__half_as_ushort(a) | ((uint32_t)__half_as_ushort(b) << 16);
}
// fp16 2-way split: v = h1 + h2 with |h2| ~ 2^-11 |v|
__device__ __forceinline__ void split2h(float vx, float vy, uint32_t& p1, uint32_t& p2) {
    __half hx = __float2half_rn(vx);
    __half hy = __float2half_rn(vy);
    float rx = vx - __half2float(hx);
    float ry = vy - __half2float(hy);
    p1 = pack_h2(hx, hy);
    p2 = cvt_h2(rx, ry);
}
__device__ __forceinline__ float tanh_ap(float x) {
    float y;
    asm("tanh.approx.f32 %0, %1;" : "=f"(y) : "f"(x));
    return y;
}
__device__ __forceinline__ void mma_f16(float* d, const uint32_t* a, uint32_t b0, uint32_t b1) {
    asm volatile(
        "mma.sync.aligned.m16n8k16.row.col.f32.f16.f16.f32 "
        "{%0,%1,%2,%3}, {%4,%5,%6,%7}, {%8,%9}, {%0,%1,%2,%3};"
        : "+f"(d[0]), "+f"(d[1]), "+f"(d[2]), "+f"(d[3])
        : "r"(a[0]), "r"(a[1]), "r"(a[2]), "r"(a[3]), "r"(b0), "r"(b1));
}

// ---------------- single fused kernel ----------------
extern "C" __global__ void __launch_bounds__(THREADS, 2)
stein_main(const float* __restrict__ x,
           const float* __restrict__ W1,
           const float* __restrict__ b1,
           const float* __restrict__ W2,
           const float* __restrict__ b2,
           const float* __restrict__ theta,
           float* __restrict__ out)
{
    __shared__ uint32_t s_Bfz[2048];   // z GEMM frags: B[n][k] = W1[k][n]  (8 KB)
    __shared__ uint32_t s_Bfv[2048];   // v GEMM frags: B[n][k] = W2[n][k]  (8 KB)
    __shared__ float s_cs[H];
    __shared__ float s_b1[H];
    __shared__ float s_red[4];
    __shared__ float s_part[PASS_ROWS][2];

    const int tid  = threadIdx.x;
    const int lane = tid & 31;
    const int w    = tid >> 5;       // 0..7
    const int mh   = w >> 1;         // 0..3 : 32-row slab within the 128-row pass
    const int kh   = w & 1;          // hidden-unit half (cols 0-63 / 64-127)
    const int row0 = blockIdx.x * ROWS_CTA;

    // ---- z-frag build: coalesced W1 row reads (thread n = tid&127) ----
    {
        const int n = tid & 127;
        const int itbase = (tid >> 7) * 8;
        #pragma unroll
        for (int q = 0; q < 8; q++) {
            const int it = itbase + q;
            const int ks = it >> 3, jj = (it >> 2) & 1, t = it & 3;
            const int k0 = ks * 16 + 2 * t + jj * 8;
            const float w0 = __ldg(W1 + k0 * H + n);
            const float w1 = __ldg(W1 + (k0 + 1) * H + n);
            const int nt = n >> 3;
            const int l  = (n & 7) * 4 + t;
            s_Bfz[((nt * 2 + ks) * 32 + l) * 2 + jj] = cvt_h2(w0, w1);
        }
    }
    // ---- v-frag build: linear float2 reads of W2 ----
    #pragma unroll
    for (int q = 0; q < 8; q++) {
        const int f = q * THREADS + tid;
        const float2 v = __ldg((const float2*)W2 + f);
        const int np = f >> 4;
        const int k0 = (f & 15) * 2;
        const int nt = np >> 3;
        const int ks = k0 >> 4, r = k0 & 15;
        const int jj = r >> 3, t = (r & 7) >> 1;
        const int l  = (np & 7) * 4 + t;
        s_Bfv[((nt * 2 + ks) * 32 + l) * 2 + jj] = cvt_h2(v.x, v.y);
    }
    // ---- c_k (tid<128) + deterministic Ctot reduction ; b1 staging (tid>=128) ----
    if (tid < H) {
        const int k = tid;
        const float4* w2r = (const float4*)(W2 + k * D);
        float c = 0.0f;
        #pragma unroll
        for (int i = 0; i < D; i += 4) {
            float4 wv = __ldg(w2r + (i >> 2));
            c = fmaf(__ldg(W1 + (i + 0) * H + k), wv.x, c);
            c = fmaf(__ldg(W1 + (i + 1) * H + k), wv.y, c);
            c = fmaf(__ldg(W1 + (i + 2) * H + k), wv.z, c);
            c = fmaf(__ldg(W1 + (i + 3) * H + k), wv.w, c);
        }
        s_cs[k] = c;
        float cr = c;
        #pragma unroll
        for (int o = 16; o; o >>= 1) cr += __shfl_xor_sync(0xFFFFFFFFu, cr, o);
        if (lane == 0) s_red[w] = cr;   // warps 0..3 fully cover tid<128
    } else {
        s_b1[tid - H] = __ldg(b1 + tid - H);
    }

    // per-lane b2 pairs for the fold (cols c=ks*16+2t and c+8)
    const int k0l = 2 * (lane & 3);
    float2 b2p[2][2];
    #pragma unroll
    for (int ks = 0; ks < 2; ks++) {
        b2p[ks][0] = __ldg((const float2*)(b2 + ks * 16 + k0l));
        b2p[ks][1] = __ldg((const float2*)(b2 + ks * 16 + k0l + 8));
    }
    const float theta_v = __ldg(theta);

    __syncthreads();   // frag tables / s_cs / s_b1 / s_red ready

    // row-independent constant: theta + sum_k c_k
    const float addc = theta_v + ((s_red[0] + s_red[1]) + (s_red[2] + s_red[3]));

    // ================= two passes of 128 rows =================
    for (int s = 0; s < 2; s++) {
        const int Mbase = row0 + s * PASS_ROWS + mh * 32;

        float psum[4] = {0.f, 0.f, 0.f, 0.f};

        // ---- A fragments + fold -x.b2 (kh==0 warps only) ----
        uint32_t a1[2][2][4], a2[2][2][4];        // [mt][ks][frag]
        #pragma unroll
        for (int mt = 0; mt < 2; mt++) {
            const int r = Mbase + mt * 16 + (lane >> 2);
            #pragma unroll
            for (int ks = 0; ks < 2; ks++) {
                const int c = ks * 16 + k0l;
                float2 v00 = __ldg((const float2*)(x + (size_t)r       * D + c));
                float2 v10 = __ldg((const float2*)(x + (size_t)(r + 8) * D + c));
                float2 v01 = __ldg((const float2*)(x + (size_t)r       * D + c + 8));
                float2 v11 = __ldg((const float2*)(x + (size_t)(r + 8) * D + c + 8));
                split2h(v00.x, v00.y, a1[mt][ks][0], a2[mt][ks][0]);
                split2h(v10.x, v10.y, a1[mt][ks][1], a2[mt][ks][1]);
                split2h(v01.x, v01.y, a1[mt][ks][2], a2[mt][ks][2]);
                split2h(v11.x, v11.y, a1[mt][ks][3], a2[mt][ks][3]);
                if (kh == 0) {
                    float& p0 = psum[mt * 2 + 0];
                    float& p1r = psum[mt * 2 + 1];
                    p0  = fmaf(-v00.x, b2p[ks][0].x, p0);
                    p0  = fmaf(-v00.y, b2p[ks][0].y, p0);
                    p0  = fmaf(-v01.x, b2p[ks][1].x, p0);
                    p0  = fmaf(-v01.y, b2p[ks][1].y, p0);
                    p1r = fmaf(-v10.x, b2p[ks][0].x, p1r);
                    p1r = fmaf(-v10.y, b2p[ks][0].y, p1r);
                    p1r = fmaf(-v11.x, b2p[ks][1].x, p1r);
                    p1r = fmaf(-v11.y, b2p[ks][1].y, p1r);
                }
            }
        }

        // ---- mainloop: per-p MMA slab (2-pass fp16), folded into psum ----
        #pragma unroll 4
        for (int p = 0; p < 8; p++) {
            const int nt = kh * 8 + p;
            const int kbase = kh * 64 + p * 8 + k0l;
            uint2 bz[2], bv[2];                   // [ks] — LDS.64, conflict-free
            #pragma unroll
            for (int ks = 0; ks < 2; ks++) {
                bz[ks] = *(const uint2*)&s_Bfz[((nt * 2 + ks) * 32 + lane) * 2];
                bv[ks] = *(const uint2*)&s_Bfv[((nt * 2 + ks) * 32 + lane) * 2];
            }
            const float2 b1p = *(const float2*)(s_b1 + kbase);
            const float2 csp = *(const float2*)(s_cs + kbase);

            // accz initialized with b1 (kills the z+b1 add in the epilogue)
            float accz[2][4], accv[2][4];         // [mt][frag]
            #pragma unroll
            for (int mt = 0; mt < 2; mt++) {
                accz[mt][0] = b1p.x; accz[mt][1] = b1p.y;
                accz[mt][2] = b1p.x; accz[mt][3] = b1p.y;
                accv[mt][0] = 0.f; accv[mt][1] = 0.f;
                accv[mt][2] = 0.f; accv[mt][3] = 0.f;
            }

            #pragma unroll
            for (int mt = 0; mt < 2; mt++)
                #pragma unroll
                for (int ks = 0; ks < 2; ks++) {
                    mma_f16(accz[mt], a1[mt][ks], bz[ks].x, bz[ks].y);  // h1
                    mma_f16(accv[mt], a1[mt][ks], bv[ks].x, bv[ks].y);
                    mma_f16(accz[mt], a2[mt][ks], bz[ks].x, bz[ks].y);  // h2
                    mma_f16(accv[mt], a2[mt][ks], bv[ks].x, bv[ks].y);
                }

            // --- epilogue: ps += c_k - h*(h*c_k + v), with Sum(c_k) hoisted ---
            #pragma unroll
            for (int j = 0; j < 2; j++) {
                const float ck = j ? csp.y : csp.x;
                #pragma unroll
                for (int mt = 0; mt < 2; mt++)
                    #pragma unroll
                    for (int rs = 0; rs < 2; rs++) {
                        float h = tanh_ap(accz[mt][rs * 2 + j]);
                        float t = fmaf(h, ck, accv[mt][rs * 2 + j]);
                        psum[mt * 2 + rs] = fmaf(-h, t, psum[mt * 2 + rs]);
                    }
            }
        }

        // ---- quad reduction + combine halves + write ----
        #pragma unroll
        for (int i = 0; i < 4; i++) {
            psum[i] += __shfl_xor_sync(0xFFFFFFFFu, psum[i], 1);
            psum[i] += __shfl_xor_sync(0xFFFFFFFFu, psum[i], 2);
        }
        if ((lane & 3) == 0) {
            const int rbase = mh * 32 + (lane >> 2);
            s_part[rbase +  0][kh] = psum[0];
            s_part[rbase +  8][kh] = psum[1];
            s_part[rbase + 16][kh] = psum[2];
            s_part[rbase + 24][kh] = psum[3];
        }
        __syncthreads();
        if (tid < PASS_ROWS)
            out[row0 + s * PASS_ROWS + tid] = s_part[tid][0] + s_part[tid][1] + addc;
        if (s == 0) __syncthreads();   // protect s_part reuse
    }
}

extern "C" void kernel_launch(void* const* d_in, const int* in_sizes, int n_in,
                              void* d_out, int out_size)
{
    const float* x     = (const float*)d_in[0];
    const float* W1    = (const float*)d_in[1];
    const float* b1    = (const float*)d_in[2];
    const float* W2    = (const float*)d_in[3];
    const float* b2    = (const float*)d_in[4];
    const float* theta = (const float*)d_in[5];
    float*       out   = (float*)d_out;

    const int nrows = in_sizes[0] / D;          // 65536
    const int grid  = nrows / ROWS_CTA;         // 256

    stein_main<<<grid, THREADS>>>(x, W1, b1, W2, b2, theta, out);
}